// round 11
// baseline (speedup 1.0000x reference)
#include <cuda_runtime.h>

// Batched per-object 3-layer MLP — 3 kernels, PDL-chained.
// R11: K2 prefetches 4 W2 rows pre-gridsync (fills K1's drain window with
// W2 traffic); K1 epilogue vectorized (float4 b1 loads / y1 stores).
//
//   K1: y1 = W1 @ x + b1                    (256 MB stream, 8 warps x 8 rows)
//   K2: 32 rows of y2 per CTA + W3 partial  (512 MB stream)
//   K3: out[o] = sigmoid(sum partials + b3)

#define N_OBJ_  2048
#define IN_DIM_ 128
#define MID_    256

__device__ float g_y1[N_OBJ_ * MID_];
__device__ float g_part[8 * N_OBJ_];   // [chunk][object]

__device__ __forceinline__ float dot4(float4 a, float4 b) {
    return fmaf(a.x, b.x, fmaf(a.y, b.y, fmaf(a.z, b.z, a.w * b.w)));
}

__device__ __forceinline__ float sigmoidf_(float t) {
    return 1.0f / (1.0f + __expf(-t));
}

__device__ __forceinline__ void warp_sum8(float (&p)[8]) {
#pragma unroll
    for (int off = 16; off > 0; off >>= 1) {
#pragma unroll
        for (int j = 0; j < 8; ++j)
            p[j] += __shfl_xor_sync(0xffffffffu, p[j], off);
    }
}

// ---- K1: 64 rows per CTA, 8 warps x 8 rows, single pass ----
__global__ __launch_bounds__(256, 6)
void k1_fc1(const float* __restrict__ x,
            const float* __restrict__ W1,
            const float* __restrict__ b1)
{
    cudaTriggerProgrammaticLaunchCompletion();

    const int o     = blockIdx.x >> 2;       // 4 chunks of 64 rows
    const int chunk = blockIdx.x & 3;
    const int warp  = threadIdx.x >> 5;
    const int lane  = threadIdx.x & 31;

    const float4 xv =
        reinterpret_cast<const float4*>(x + (size_t)o * IN_DIM_)[lane];
    const int row0 = chunk * 64 + warp * 8;
    // row stride = 128 floats = 32 float4
    const float4* Wr = reinterpret_cast<const float4*>(
                           W1 + (size_t)o * MID_ * IN_DIM_ +
                           (size_t)row0 * IN_DIM_) + lane;

    float part[8];
#pragma unroll
    for (int b = 0; b < 2; ++b) {
        const float4 w0 = Wr[(b * 4 + 0) * 32];
        const float4 w1 = Wr[(b * 4 + 1) * 32];
        const float4 w2 = Wr[(b * 4 + 2) * 32];
        const float4 w3 = Wr[(b * 4 + 3) * 32];
        part[b * 4 + 0] = dot4(w0, xv);
        part[b * 4 + 1] = dot4(w1, xv);
        part[b * 4 + 2] = dot4(w2, xv);
        part[b * 4 + 3] = dot4(w3, xv);
    }

    warp_sum8(part);

    if (lane == 0) {
        const float4* b1v =
            reinterpret_cast<const float4*>(b1 + o * MID_ + row0);
        const float4 ba = b1v[0];
        const float4 bb = b1v[1];
        float4* y1v = reinterpret_cast<float4*>(g_y1 + o * MID_ + row0);
        y1v[0] = make_float4(part[0] + ba.x, part[1] + ba.y,
                             part[2] + ba.z, part[3] + ba.w);
        y1v[1] = make_float4(part[4] + bb.x, part[5] + bb.y,
                             part[6] + bb.z, part[7] + bb.w);
    }
}

// ---- K2: 32 rows of y2 per CTA + W3 partial; 4-row W2 prefetch ----
__global__ __launch_bounds__(128, 8)
void k2_fc2(const float* __restrict__ W2,
            const float* __restrict__ b2,
            const float* __restrict__ W3)
{
    cudaTriggerProgrammaticLaunchCompletion();

    const int o     = blockIdx.x >> 3;
    const int chunk = blockIdx.x & 7;
    const int warp  = threadIdx.x >> 5;
    const int lane  = threadIdx.x & 31;

    const int row0 = chunk * 32 + warp * 8;
    const float4* Wr = reinterpret_cast<const float4*>(
                           W2 + (size_t)o * MID_ * MID_ +
                           (size_t)row0 * MID_) + lane;

    // Prefetch rows 0-3 (pure input — legal pre-sync; overlaps K1 drain).
    const float4 p0a = Wr[0],           p0b = Wr[32];
    const float4 p1a = Wr[64],          p1b = Wr[96];
    const float4 p2a = Wr[128],         p2b = Wr[160];
    const float4 p3a = Wr[192],         p3b = Wr[224];

    cudaGridDependencySynchronize();

    const float4* y1v = reinterpret_cast<const float4*>(g_y1 + o * MID_);
    const float4 ya = y1v[lane];
    const float4 yb = y1v[32 + lane];

    float part[8];
    part[0] = fmaf(p0a.x, ya.x, fmaf(p0a.y, ya.y, fmaf(p0a.z, ya.z,
              fmaf(p0a.w, ya.w, dot4(p0b, yb)))));
    part[1] = fmaf(p1a.x, ya.x, fmaf(p1a.y, ya.y, fmaf(p1a.z, ya.z,
              fmaf(p1a.w, ya.w, dot4(p1b, yb)))));
    part[2] = fmaf(p2a.x, ya.x, fmaf(p2a.y, ya.y, fmaf(p2a.z, ya.z,
              fmaf(p2a.w, ya.w, dot4(p2b, yb)))));
    part[3] = fmaf(p3a.x, ya.x, fmaf(p3a.y, ya.y, fmaf(p3a.z, ya.z,
              fmaf(p3a.w, ya.w, dot4(p3b, yb)))));

#pragma unroll
    for (int b = 2; b < 4; ++b) {
        const float4 a0 = Wr[(2 * b)     * 64];
        const float4 a1 = Wr[(2 * b)     * 64 + 32];
        const float4 c0 = Wr[(2 * b + 1) * 64];
        const float4 c1 = Wr[(2 * b + 1) * 64 + 32];
        part[2 * b]     = fmaf(a0.x, ya.x, fmaf(a0.y, ya.y, fmaf(a0.z, ya.z,
                          fmaf(a0.w, ya.w, dot4(a1, yb)))));
        part[2 * b + 1] = fmaf(c0.x, ya.x, fmaf(c0.y, ya.y, fmaf(c0.z, ya.z,
                          fmaf(c0.w, ya.w, dot4(c1, yb)))));
    }

    warp_sum8(part);

    __shared__ float sp[4];
    if (lane == 0) {
        const float* b2o = b2 + o * MID_ + row0;
        const float* W3o = W3 + o * MID_ + row0;
        float p = 0.0f;
#pragma unroll
        for (int j = 0; j < 8; ++j)
            p = fmaf(W3o[j], sigmoidf_(part[j] + b2o[j]), p);
        sp[warp] = p;
    }
    __syncthreads();   // convergent barrier
    if (threadIdx.x == 0)
        g_part[chunk * N_OBJ_ + o] = sp[0] + sp[1] + sp[2] + sp[3];
}

// ---- K3: thread-per-object reduction + sigmoid ----
__global__ __launch_bounds__(128)
void k3_final(const float* __restrict__ b3, float* __restrict__ out)
{
    cudaGridDependencySynchronize();

    const int o = blockIdx.x * 128 + threadIdx.x;
    float s = b3[o];
#pragma unroll
    for (int c = 0; c < 8; ++c)
        s += g_part[c * N_OBJ_ + o];
    out[o] = sigmoidf_(s);
}

extern "C" void kernel_launch(void* const* d_in, const int* in_sizes, int n_in,
                              void* d_out, int out_size)
{
    const float* x  = (const float*)d_in[0];
    const float* W1 = (const float*)d_in[1];
    const float* b1 = (const float*)d_in[2];
    const float* W2 = (const float*)d_in[3];
    const float* b2 = (const float*)d_in[4];
    const float* W3 = (const float*)d_in[5];
    const float* b3 = (const float*)d_in[6];
    float* out = (float*)d_out;

    k1_fc1<<<N_OBJ_ * 4, 256>>>(x, W1, b1);

    cudaLaunchAttribute attr[1];
    attr[0].id = cudaLaunchAttributeProgrammaticStreamSerialization;
    attr[0].val.programmaticStreamSerializationAllowed = 1;

    {
        cudaLaunchConfig_t cfg = {};
        cfg.gridDim  = dim3(N_OBJ_ * 8);
        cfg.blockDim = dim3(128);
        cfg.stream   = 0;
        cfg.attrs    = attr;
        cfg.numAttrs = 1;
        cudaLaunchKernelEx(&cfg, k2_fc2, W2, b2, W3);
    }
    {
        cudaLaunchConfig_t cfg = {};
        cfg.gridDim  = dim3(N_OBJ_ / 128);
        cfg.blockDim = dim3(128);
        cfg.stream   = 0;
        cfg.attrs    = attr;
        cfg.numAttrs = 1;
        cudaLaunchKernelEx(&cfg, k3_final, b3, out);
    }
}

// round 12
// speedup vs baseline: 1.0161x; 1.0161x over previous
#include <cuda_runtime.h>

// Batched per-object 3-layer MLP — 3 kernels, PDL-chained.
// R12: exact R10 config, except K2 adopts K1's winning 256-thread CTA shape
// (8 warps x 8 rows = 64-row slab, grid 8192, single pass).
//
//   K1: y1 = W1 @ x + b1                    (256 MB stream)
//   K2: 64 rows of y2 per CTA + W3 partial  (512 MB stream, 2-row prefetch)
//   K3: out[o] = sigmoid(sum partials + b3)

#define N_OBJ_  2048
#define IN_DIM_ 128
#define MID_    256

__device__ float g_y1[N_OBJ_ * MID_];
__device__ float g_part[4 * N_OBJ_];   // [chunk][object]

__device__ __forceinline__ float dot4(float4 a, float4 b) {
    return fmaf(a.x, b.x, fmaf(a.y, b.y, fmaf(a.z, b.z, a.w * b.w)));
}

__device__ __forceinline__ float sigmoidf_(float t) {
    return 1.0f / (1.0f + __expf(-t));
}

__device__ __forceinline__ void warp_sum8(float (&p)[8]) {
#pragma unroll
    for (int off = 16; off > 0; off >>= 1) {
#pragma unroll
        for (int j = 0; j < 8; ++j)
            p[j] += __shfl_xor_sync(0xffffffffu, p[j], off);
    }
}

// ---- K1: 64 rows per CTA, 8 warps x 8 rows, single pass (R10 exact) ----
__global__ __launch_bounds__(256, 6)
void k1_fc1(const float* __restrict__ x,
            const float* __restrict__ W1,
            const float* __restrict__ b1)
{
    cudaTriggerProgrammaticLaunchCompletion();

    const int o     = blockIdx.x >> 2;       // 4 chunks of 64 rows
    const int chunk = blockIdx.x & 3;
    const int warp  = threadIdx.x >> 5;
    const int lane  = threadIdx.x & 31;

    const float4 xv =
        reinterpret_cast<const float4*>(x + (size_t)o * IN_DIM_)[lane];
    const int row0 = chunk * 64 + warp * 8;
    // row stride = 128 floats = 32 float4
    const float4* Wr = reinterpret_cast<const float4*>(
                           W1 + (size_t)o * MID_ * IN_DIM_ +
                           (size_t)row0 * IN_DIM_) + lane;

    float part[8];
#pragma unroll
    for (int b = 0; b < 2; ++b) {
        const float4 w0 = Wr[(b * 4 + 0) * 32];
        const float4 w1 = Wr[(b * 4 + 1) * 32];
        const float4 w2 = Wr[(b * 4 + 2) * 32];
        const float4 w3 = Wr[(b * 4 + 3) * 32];
        part[b * 4 + 0] = dot4(w0, xv);
        part[b * 4 + 1] = dot4(w1, xv);
        part[b * 4 + 2] = dot4(w2, xv);
        part[b * 4 + 3] = dot4(w3, xv);
    }

    warp_sum8(part);

    if (lane == 0) {
        const float* b1o = b1 + o * MID_ + row0;
        float* y1o = g_y1 + o * MID_ + row0;
#pragma unroll
        for (int j = 0; j < 8; ++j)
            y1o[j] = part[j] + b1o[j];
    }
}

// ---- K2: 64 rows per CTA, 8 warps x 8 rows; 2-row prefetch pre-gridsync ----
__global__ __launch_bounds__(256, 5)
void k2_fc2(const float* __restrict__ W2,
            const float* __restrict__ b2,
            const float* __restrict__ W3)
{
    cudaTriggerProgrammaticLaunchCompletion();

    const int o     = blockIdx.x >> 2;       // 4 chunks of 64 rows
    const int chunk = blockIdx.x & 3;
    const int warp  = threadIdx.x >> 5;
    const int lane  = threadIdx.x & 31;

    const int row0 = chunk * 64 + warp * 8;
    // row stride = 256 floats = 64 float4
    const float4* Wr = reinterpret_cast<const float4*>(
                           W2 + (size_t)o * MID_ * MID_ +
                           (size_t)row0 * MID_) + lane;

    // Prefetch rows 0,1 (pure input — legal pre-sync).
    const float4 p_a0 = Wr[0];
    const float4 p_a1 = Wr[32];
    const float4 p_c0 = Wr[64];
    const float4 p_c1 = Wr[96];

    cudaGridDependencySynchronize();

    const float4* y1v = reinterpret_cast<const float4*>(g_y1 + o * MID_);
    const float4 ya = y1v[lane];
    const float4 yb = y1v[32 + lane];

    float part[8];
    part[0] = fmaf(p_a0.x, ya.x, fmaf(p_a0.y, ya.y, fmaf(p_a0.z, ya.z,
              fmaf(p_a0.w, ya.w, dot4(p_a1, yb)))));
    part[1] = fmaf(p_c0.x, ya.x, fmaf(p_c0.y, ya.y, fmaf(p_c0.z, ya.z,
              fmaf(p_c0.w, ya.w, dot4(p_c1, yb)))));

#pragma unroll
    for (int b = 1; b < 4; ++b) {
        const float4 a0 = Wr[(2 * b)     * 64];
        const float4 a1 = Wr[(2 * b)     * 64 + 32];
        const float4 c0 = Wr[(2 * b + 1) * 64];
        const float4 c1 = Wr[(2 * b + 1) * 64 + 32];
        part[2 * b]     = fmaf(a0.x, ya.x, fmaf(a0.y, ya.y, fmaf(a0.z, ya.z,
                          fmaf(a0.w, ya.w, dot4(a1, yb)))));
        part[2 * b + 1] = fmaf(c0.x, ya.x, fmaf(c0.y, ya.y, fmaf(c0.z, ya.z,
                          fmaf(c0.w, ya.w, dot4(c1, yb)))));
    }

    warp_sum8(part);

    __shared__ float sp[8];
    if (lane == 0) {
        const float* b2o = b2 + o * MID_ + row0;
        const float* W3o = W3 + o * MID_ + row0;
        float p = 0.0f;
#pragma unroll
        for (int j = 0; j < 8; ++j)
            p = fmaf(W3o[j], sigmoidf_(part[j] + b2o[j]), p);
        sp[warp] = p;
    }
    __syncthreads();   // convergent barrier
    if (threadIdx.x == 0) {
        float t = 0.0f;
#pragma unroll
        for (int w = 0; w < 8; ++w) t += sp[w];
        g_part[chunk * N_OBJ_ + o] = t;
    }
}

// ---- K3: thread-per-object reduction + sigmoid ----
__global__ __launch_bounds__(128)
void k3_final(const float* __restrict__ b3, float* __restrict__ out)
{
    cudaGridDependencySynchronize();

    const int o = blockIdx.x * 128 + threadIdx.x;
    float s = b3[o];
#pragma unroll
    for (int c = 0; c < 4; ++c)
        s += g_part[c * N_OBJ_ + o];
    out[o] = sigmoidf_(s);
}

extern "C" void kernel_launch(void* const* d_in, const int* in_sizes, int n_in,
                              void* d_out, int out_size)
{
    const float* x  = (const float*)d_in[0];
    const float* W1 = (const float*)d_in[1];
    const float* b1 = (const float*)d_in[2];
    const float* W2 = (const float*)d_in[3];
    const float* b2 = (const float*)d_in[4];
    const float* W3 = (const float*)d_in[5];
    const float* b3 = (const float*)d_in[6];
    float* out = (float*)d_out;

    k1_fc1<<<N_OBJ_ * 4, 256>>>(x, W1, b1);

    cudaLaunchAttribute attr[1];
    attr[0].id = cudaLaunchAttributeProgrammaticStreamSerialization;
    attr[0].val.programmaticStreamSerializationAllowed = 1;

    {
        cudaLaunchConfig_t cfg = {};
        cfg.gridDim  = dim3(N_OBJ_ * 4);
        cfg.blockDim = dim3(256);
        cfg.stream   = 0;
        cfg.attrs    = attr;
        cfg.numAttrs = 1;
        cudaLaunchKernelEx(&cfg, k2_fc2, W2, b2, W3);
    }
    {
        cudaLaunchConfig_t cfg = {};
        cfg.gridDim  = dim3(N_OBJ_ / 128);
        cfg.blockDim = dim3(128);
        cfg.stream   = 0;
        cfg.attrs    = attr;
        cfg.numAttrs = 1;
        cudaLaunchKernelEx(&cfg, k3_final, b3, out);
    }
}

// round 13
// speedup vs baseline: 1.0198x; 1.0036x over previous
#include <cuda_runtime.h>

// Batched per-object 3-layer MLP — R10 kernel bodies, work forked across two
// captured streams so the W1 phase of one half overlaps the W2 phase of the
// other (no global K1->K2 barrier).
//
//   stream0: K1(obj 0..1023)    -PDL-> K2(obj 0..1023)    \
//   s2:      K1(obj 1024..2047) -PDL-> K2(obj 1024..2047) -> join -> K3

#define N_OBJ_  2048
#define HALF_   (N_OBJ_ / 2)
#define IN_DIM_ 128
#define MID_    256

__device__ float g_y1[N_OBJ_ * MID_];
__device__ float g_part[8 * N_OBJ_];   // [chunk][object]

__device__ __forceinline__ float dot4(float4 a, float4 b) {
    return fmaf(a.x, b.x, fmaf(a.y, b.y, fmaf(a.z, b.z, a.w * b.w)));
}

__device__ __forceinline__ float sigmoidf_(float t) {
    return 1.0f / (1.0f + __expf(-t));
}

__device__ __forceinline__ void warp_sum8(float (&p)[8]) {
#pragma unroll
    for (int off = 16; off > 0; off >>= 1) {
#pragma unroll
        for (int j = 0; j < 8; ++j)
            p[j] += __shfl_xor_sync(0xffffffffu, p[j], off);
    }
}

// ---- K1: 64 rows per CTA, 8 warps x 8 rows (R10 exact, + obj_base) ----
__global__ __launch_bounds__(256, 6)
void k1_fc1(const float* __restrict__ x,
            const float* __restrict__ W1,
            const float* __restrict__ b1,
            int obj_base)
{
    cudaTriggerProgrammaticLaunchCompletion();

    const int o     = obj_base + (blockIdx.x >> 2);
    const int chunk = blockIdx.x & 3;
    const int warp  = threadIdx.x >> 5;
    const int lane  = threadIdx.x & 31;

    const float4 xv =
        reinterpret_cast<const float4*>(x + (size_t)o * IN_DIM_)[lane];
    const int row0 = chunk * 64 + warp * 8;
    const float4* Wr = reinterpret_cast<const float4*>(
                           W1 + (size_t)o * MID_ * IN_DIM_ +
                           (size_t)row0 * IN_DIM_) + lane;

    float part[8];
#pragma unroll
    for (int b = 0; b < 2; ++b) {
        const float4 w0 = Wr[(b * 4 + 0) * 32];
        const float4 w1 = Wr[(b * 4 + 1) * 32];
        const float4 w2 = Wr[(b * 4 + 2) * 32];
        const float4 w3 = Wr[(b * 4 + 3) * 32];
        part[b * 4 + 0] = dot4(w0, xv);
        part[b * 4 + 1] = dot4(w1, xv);
        part[b * 4 + 2] = dot4(w2, xv);
        part[b * 4 + 3] = dot4(w3, xv);
    }

    warp_sum8(part);

    if (lane == 0) {
        const float* b1o = b1 + o * MID_ + row0;
        float* y1o = g_y1 + o * MID_ + row0;
#pragma unroll
        for (int j = 0; j < 8; ++j)
            y1o[j] = part[j] + b1o[j];
    }
}

// ---- K2: 32 rows per CTA, 128 thr, 2-row prefetch (R10 exact, + obj_base) ----
__global__ __launch_bounds__(128, 10)
void k2_fc2(const float* __restrict__ W2,
            const float* __restrict__ b2,
            const float* __restrict__ W3,
            int obj_base)
{
    cudaTriggerProgrammaticLaunchCompletion();

    const int o     = obj_base + (blockIdx.x >> 3);
    const int chunk = blockIdx.x & 7;
    const int warp  = threadIdx.x >> 5;
    const int lane  = threadIdx.x & 31;

    const int row0 = chunk * 32 + warp * 8;
    const float4* Wr = reinterpret_cast<const float4*>(
                           W2 + (size_t)o * MID_ * MID_ +
                           (size_t)row0 * MID_) + lane;

    // Prefetch rows 0,1 (pure input — legal pre-sync).
    const float4 p_a0 = Wr[0];
    const float4 p_a1 = Wr[32];
    const float4 p_c0 = Wr[64];
    const float4 p_c1 = Wr[96];

    cudaGridDependencySynchronize();

    const float4* y1v = reinterpret_cast<const float4*>(g_y1 + o * MID_);
    const float4 ya = y1v[lane];
    const float4 yb = y1v[32 + lane];

    float part[8];
    part[0] = fmaf(p_a0.x, ya.x, fmaf(p_a0.y, ya.y, fmaf(p_a0.z, ya.z,
              fmaf(p_a0.w, ya.w, dot4(p_a1, yb)))));
    part[1] = fmaf(p_c0.x, ya.x, fmaf(p_c0.y, ya.y, fmaf(p_c0.z, ya.z,
              fmaf(p_c0.w, ya.w, dot4(p_c1, yb)))));

#pragma unroll
    for (int b = 1; b < 4; ++b) {
        const float4 a0 = Wr[(2 * b)     * 64];
        const float4 a1 = Wr[(2 * b)     * 64 + 32];
        const float4 c0 = Wr[(2 * b + 1) * 64];
        const float4 c1 = Wr[(2 * b + 1) * 64 + 32];
        part[2 * b]     = fmaf(a0.x, ya.x, fmaf(a0.y, ya.y, fmaf(a0.z, ya.z,
                          fmaf(a0.w, ya.w, dot4(a1, yb)))));
        part[2 * b + 1] = fmaf(c0.x, ya.x, fmaf(c0.y, ya.y, fmaf(c0.z, ya.z,
                          fmaf(c0.w, ya.w, dot4(c1, yb)))));
    }

    warp_sum8(part);

    __shared__ float sp[4];
    if (lane == 0) {
        const float* b2o = b2 + o * MID_ + row0;
        const float* W3o = W3 + o * MID_ + row0;
        float p = 0.0f;
#pragma unroll
        for (int j = 0; j < 8; ++j)
            p = fmaf(W3o[j], sigmoidf_(part[j] + b2o[j]), p);
        sp[warp] = p;
    }
    __syncthreads();
    if (threadIdx.x == 0)
        g_part[chunk * N_OBJ_ + o] = sp[0] + sp[1] + sp[2] + sp[3];
}

// ---- K3: thread-per-object reduction + sigmoid ----
__global__ __launch_bounds__(128)
void k3_final(const float* __restrict__ b3, float* __restrict__ out)
{
    const int o = blockIdx.x * 128 + threadIdx.x;
    float s = b3[o];
#pragma unroll
    for (int c = 0; c < 8; ++c)
        s += g_part[c * N_OBJ_ + o];
    out[o] = sigmoidf_(s);
}

extern "C" void kernel_launch(void* const* d_in, const int* in_sizes, int n_in,
                              void* d_out, int out_size)
{
    const float* x  = (const float*)d_in[0];
    const float* W1 = (const float*)d_in[1];
    const float* b1 = (const float*)d_in[2];
    const float* W2 = (const float*)d_in[3];
    const float* b2 = (const float*)d_in[4];
    const float* W3 = (const float*)d_in[5];
    const float* b3 = (const float*)d_in[6];
    float* out = (float*)d_out;

    // Created once on the first (correctness, non-captured) call; the GPU
    // work issued per call is identical every time.
    static cudaStream_t s2 = []() {
        cudaStream_t s; cudaStreamCreateWithFlags(&s, cudaStreamNonBlocking);
        return s;
    }();
    static cudaEvent_t ev_fork = []() {
        cudaEvent_t e; cudaEventCreateWithFlags(&e, cudaEventDisableTiming);
        return e;
    }();
    static cudaEvent_t ev_join = []() {
        cudaEvent_t e; cudaEventCreateWithFlags(&e, cudaEventDisableTiming);
        return e;
    }();

    cudaLaunchAttribute attr[1];
    attr[0].id = cudaLaunchAttributeProgrammaticStreamSerialization;
    attr[0].val.programmaticStreamSerializationAllowed = 1;

    // Fork: s2 joins the capture via the fork event.
    cudaEventRecord(ev_fork, 0);
    cudaStreamWaitEvent(s2, ev_fork, 0);

    // K1 halves (plain launches, one per stream)
    k1_fc1<<<HALF_ * 4, 256, 0, 0 >>>(x, W1, b1, 0);
    k1_fc1<<<HALF_ * 4, 256, 0, s2>>>(x, W1, b1, HALF_);

    // K2 halves, PDL-chained after their stream's K1
    {
        cudaLaunchConfig_t cfg = {};
        cfg.gridDim  = dim3(HALF_ * 8);
        cfg.blockDim = dim3(128);
        cfg.stream   = 0;
        cfg.attrs    = attr;
        cfg.numAttrs = 1;
        cudaLaunchKernelEx(&cfg, k2_fc2, W2, b2, W3, 0);
    }
    {
        cudaLaunchConfig_t cfg = {};
        cfg.gridDim  = dim3(HALF_ * 8);
        cfg.blockDim = dim3(128);
        cfg.stream   = s2;
        cfg.attrs    = attr;
        cfg.numAttrs = 1;
        cudaLaunchKernelEx(&cfg, k2_fc2, W2, b2, W3, HALF_);
    }

    // Join s2 back into stream 0, then K3.
    cudaEventRecord(ev_join, s2);
    cudaStreamWaitEvent(0, ev_join, 0);
    k3_final<<<N_OBJ_ / 128, 128, 0, 0>>>(b3, out);
}

// round 14
// speedup vs baseline: 1.0646x; 1.0440x over previous
#include <cuda_runtime.h>

// Batched per-object 3-layer MLP — 3 kernels, PDL-chained (R10 config).
// R14: weight loads use __ldcs (evict-first) so L2 retains the reused data
// (g_y1, biases, W3, partials) instead of dead weight lines.
//
//   K1: y1 = W1 @ x + b1                    (256 MB stream, 256thr/64-row)
//   K2: 32 rows of y2 per CTA + W3 partial  (512 MB stream, 128thr/32-row)
//   K3: out[o] = sigmoid(sum partials + b3)

#define N_OBJ_  2048
#define IN_DIM_ 128
#define MID_    256

__device__ float g_y1[N_OBJ_ * MID_];
__device__ float g_part[8 * N_OBJ_];   // [chunk][object]

__device__ __forceinline__ float dot4(float4 a, float4 b) {
    return fmaf(a.x, b.x, fmaf(a.y, b.y, fmaf(a.z, b.z, a.w * b.w)));
}

__device__ __forceinline__ float sigmoidf_(float t) {
    return 1.0f / (1.0f + __expf(-t));
}

__device__ __forceinline__ void warp_sum8(float (&p)[8]) {
#pragma unroll
    for (int off = 16; off > 0; off >>= 1) {
#pragma unroll
        for (int j = 0; j < 8; ++j)
            p[j] += __shfl_xor_sync(0xffffffffu, p[j], off);
    }
}

// ---- K1: 64 rows per CTA, 8 warps x 8 rows, single pass ----
__global__ __launch_bounds__(256, 6)
void k1_fc1(const float* __restrict__ x,
            const float* __restrict__ W1,
            const float* __restrict__ b1)
{
    cudaTriggerProgrammaticLaunchCompletion();

    const int o     = blockIdx.x >> 2;       // 4 chunks of 64 rows
    const int chunk = blockIdx.x & 3;
    const int warp  = threadIdx.x >> 5;
    const int lane  = threadIdx.x & 31;

    const float4 xv =
        reinterpret_cast<const float4*>(x + (size_t)o * IN_DIM_)[lane];
    const int row0 = chunk * 64 + warp * 8;
    // row stride = 128 floats = 32 float4
    const float4* Wr = reinterpret_cast<const float4*>(
                           W1 + (size_t)o * MID_ * IN_DIM_ +
                           (size_t)row0 * IN_DIM_) + lane;

    float part[8];
#pragma unroll
    for (int b = 0; b < 2; ++b) {
        const float4 w0 = __ldcs(Wr + (b * 4 + 0) * 32);
        const float4 w1 = __ldcs(Wr + (b * 4 + 1) * 32);
        const float4 w2 = __ldcs(Wr + (b * 4 + 2) * 32);
        const float4 w3 = __ldcs(Wr + (b * 4 + 3) * 32);
        part[b * 4 + 0] = dot4(w0, xv);
        part[b * 4 + 1] = dot4(w1, xv);
        part[b * 4 + 2] = dot4(w2, xv);
        part[b * 4 + 3] = dot4(w3, xv);
    }

    warp_sum8(part);

    if (lane == 0) {
        const float* b1o = b1 + o * MID_ + row0;
        float* y1o = g_y1 + o * MID_ + row0;
#pragma unroll
        for (int j = 0; j < 8; ++j)
            y1o[j] = part[j] + b1o[j];
    }
}

// ---- K2: 32 rows per CTA, 128 thr, 2-row prefetch pre-gridsync ----
__global__ __launch_bounds__(128, 10)
void k2_fc2(const float* __restrict__ W2,
            const float* __restrict__ b2,
            const float* __restrict__ W3)
{
    cudaTriggerProgrammaticLaunchCompletion();

    const int o     = blockIdx.x >> 3;
    const int chunk = blockIdx.x & 7;
    const int warp  = threadIdx.x >> 5;
    const int lane  = threadIdx.x & 31;

    const int row0 = chunk * 32 + warp * 8;
    const float4* Wr = reinterpret_cast<const float4*>(
                           W2 + (size_t)o * MID_ * MID_ +
                           (size_t)row0 * MID_) + lane;

    // Prefetch rows 0,1 (pure input — legal pre-sync).
    const float4 p_a0 = __ldcs(Wr);
    const float4 p_a1 = __ldcs(Wr + 32);
    const float4 p_c0 = __ldcs(Wr + 64);
    const float4 p_c1 = __ldcs(Wr + 96);

    cudaGridDependencySynchronize();

    const float4* y1v = reinterpret_cast<const float4*>(g_y1 + o * MID_);
    const float4 ya = y1v[lane];
    const float4 yb = y1v[32 + lane];

    float part[8];
    part[0] = fmaf(p_a0.x, ya.x, fmaf(p_a0.y, ya.y, fmaf(p_a0.z, ya.z,
              fmaf(p_a0.w, ya.w, dot4(p_a1, yb)))));
    part[1] = fmaf(p_c0.x, ya.x, fmaf(p_c0.y, ya.y, fmaf(p_c0.z, ya.z,
              fmaf(p_c0.w, ya.w, dot4(p_c1, yb)))));

#pragma unroll
    for (int b = 1; b < 4; ++b) {
        const float4 a0 = __ldcs(Wr + (2 * b)     * 64);
        const float4 a1 = __ldcs(Wr + (2 * b)     * 64 + 32);
        const float4 c0 = __ldcs(Wr + (2 * b + 1) * 64);
        const float4 c1 = __ldcs(Wr + (2 * b + 1) * 64 + 32);
        part[2 * b]     = fmaf(a0.x, ya.x, fmaf(a0.y, ya.y, fmaf(a0.z, ya.z,
                          fmaf(a0.w, ya.w, dot4(a1, yb)))));
        part[2 * b + 1] = fmaf(c0.x, ya.x, fmaf(c0.y, ya.y, fmaf(c0.z, ya.z,
                          fmaf(c0.w, ya.w, dot4(c1, yb)))));
    }

    warp_sum8(part);

    __shared__ float sp[4];
    if (lane == 0) {
        const float* b2o = b2 + o * MID_ + row0;
        const float* W3o = W3 + o * MID_ + row0;
        float p = 0.0f;
#pragma unroll
        for (int j = 0; j < 8; ++j)
            p = fmaf(W3o[j], sigmoidf_(part[j] + b2o[j]), p);
        sp[warp] = p;
    }
    __syncthreads();   // convergent barrier
    if (threadIdx.x == 0)
        g_part[chunk * N_OBJ_ + o] = sp[0] + sp[1] + sp[2] + sp[3];
}

// ---- K3: thread-per-object reduction + sigmoid ----
__global__ __launch_bounds__(128)
void k3_final(const float* __restrict__ b3, float* __restrict__ out)
{
    cudaGridDependencySynchronize();

    const int o = blockIdx.x * 128 + threadIdx.x;
    float s = b3[o];
#pragma unroll
    for (int c = 0; c < 8; ++c)
        s += g_part[c * N_OBJ_ + o];
    out[o] = sigmoidf_(s);
}

extern "C" void kernel_launch(void* const* d_in, const int* in_sizes, int n_in,
                              void* d_out, int out_size)
{
    const float* x  = (const float*)d_in[0];
    const float* W1 = (const float*)d_in[1];
    const float* b1 = (const float*)d_in[2];
    const float* W2 = (const float*)d_in[3];
    const float* b2 = (const float*)d_in[4];
    const float* W3 = (const float*)d_in[5];
    const float* b3 = (const float*)d_in[6];
    float* out = (float*)d_out;

    k1_fc1<<<N_OBJ_ * 4, 256>>>(x, W1, b1);

    cudaLaunchAttribute attr[1];
    attr[0].id = cudaLaunchAttributeProgrammaticStreamSerialization;
    attr[0].val.programmaticStreamSerializationAllowed = 1;

    {
        cudaLaunchConfig_t cfg = {};
        cfg.gridDim  = dim3(N_OBJ_ * 8);
        cfg.blockDim = dim3(128);
        cfg.stream   = 0;
        cfg.attrs    = attr;
        cfg.numAttrs = 1;
        cudaLaunchKernelEx(&cfg, k2_fc2, W2, b2, W3);
    }
    {
        cudaLaunchConfig_t cfg = {};
        cfg.gridDim  = dim3(N_OBJ_ / 128);
        cfg.blockDim = dim3(128);
        cfg.stream   = 0;
        cfg.attrs    = attr;
        cfg.numAttrs = 1;
        cudaLaunchKernelEx(&cfg, k3_final, b3, out);
    }
}

// round 15
// speedup vs baseline: 1.0649x; 1.0003x over previous
#include <cuda_runtime.h>

// Batched per-object 3-layer MLP — 3 kernels, PDL-chained (R14 config).
// R15: K1 loads all 8 rows up front (8 independent LDG.128 in flight) and
// vectorizes the lane-0 epilogue. K2/K3 identical to R14 (__ldcs weights).
//
//   K1: y1 = W1 @ x + b1                    (256 MB stream, 256thr/64-row)
//   K2: 32 rows of y2 per CTA + W3 partial  (512 MB stream, 128thr/32-row)
//   K3: out[o] = sigmoid(sum partials + b3)

#define N_OBJ_  2048
#define IN_DIM_ 128
#define MID_    256

__device__ float g_y1[N_OBJ_ * MID_];
__device__ float g_part[8 * N_OBJ_];   // [chunk][object]

__device__ __forceinline__ float dot4(float4 a, float4 b) {
    return fmaf(a.x, b.x, fmaf(a.y, b.y, fmaf(a.z, b.z, a.w * b.w)));
}

__device__ __forceinline__ float sigmoidf_(float t) {
    return 1.0f / (1.0f + __expf(-t));
}

__device__ __forceinline__ void warp_sum8(float (&p)[8]) {
#pragma unroll
    for (int off = 16; off > 0; off >>= 1) {
#pragma unroll
        for (int j = 0; j < 8; ++j)
            p[j] += __shfl_xor_sync(0xffffffffu, p[j], off);
    }
}

// ---- K1: 64 rows per CTA, 8 warps x 8 rows; all loads front-batched ----
__global__ __launch_bounds__(256, 5)
void k1_fc1(const float* __restrict__ x,
            const float* __restrict__ W1,
            const float* __restrict__ b1)
{
    cudaTriggerProgrammaticLaunchCompletion();

    const int o     = blockIdx.x >> 2;       // 4 chunks of 64 rows
    const int chunk = blockIdx.x & 3;
    const int warp  = threadIdx.x >> 5;
    const int lane  = threadIdx.x & 31;

    const float4 xv =
        reinterpret_cast<const float4*>(x + (size_t)o * IN_DIM_)[lane];
    const int row0 = chunk * 64 + warp * 8;
    // row stride = 128 floats = 32 float4
    const float4* Wr = reinterpret_cast<const float4*>(
                           W1 + (size_t)o * MID_ * IN_DIM_ +
                           (size_t)row0 * IN_DIM_) + lane;

    // 8 independent LDG.128 in flight
    float4 w[8];
#pragma unroll
    for (int j = 0; j < 8; ++j)
        w[j] = __ldcs(Wr + j * 32);

    float part[8];
#pragma unroll
    for (int j = 0; j < 8; ++j)
        part[j] = dot4(w[j], xv);

    warp_sum8(part);

    if (lane == 0) {
        const float4* b1v =
            reinterpret_cast<const float4*>(b1 + o * MID_ + row0);
        const float4 ba = b1v[0];
        const float4 bb = b1v[1];
        float4* y1v = reinterpret_cast<float4*>(g_y1 + o * MID_ + row0);
        y1v[0] = make_float4(part[0] + ba.x, part[1] + ba.y,
                             part[2] + ba.z, part[3] + ba.w);
        y1v[1] = make_float4(part[4] + bb.x, part[5] + bb.y,
                             part[6] + bb.z, part[7] + bb.w);
    }
}

// ---- K2: 32 rows per CTA, 128 thr, 2-row prefetch (R14 exact) ----
__global__ __launch_bounds__(128, 10)
void k2_fc2(const float* __restrict__ W2,
            const float* __restrict__ b2,
            const float* __restrict__ W3)
{
    cudaTriggerProgrammaticLaunchCompletion();

    const int o     = blockIdx.x >> 3;
    const int chunk = blockIdx.x & 7;
    const int warp  = threadIdx.x >> 5;
    const int lane  = threadIdx.x & 31;

    const int row0 = chunk * 32 + warp * 8;
    const float4* Wr = reinterpret_cast<const float4*>(
                           W2 + (size_t)o * MID_ * MID_ +
                           (size_t)row0 * MID_) + lane;

    // Prefetch rows 0,1 (pure input — legal pre-sync).
    const float4 p_a0 = __ldcs(Wr);
    const float4 p_a1 = __ldcs(Wr + 32);
    const float4 p_c0 = __ldcs(Wr + 64);
    const float4 p_c1 = __ldcs(Wr + 96);

    cudaGridDependencySynchronize();

    const float4* y1v = reinterpret_cast<const float4*>(g_y1 + o * MID_);
    const float4 ya = y1v[lane];
    const float4 yb = y1v[32 + lane];

    float part[8];
    part[0] = fmaf(p_a0.x, ya.x, fmaf(p_a0.y, ya.y, fmaf(p_a0.z, ya.z,
              fmaf(p_a0.w, ya.w, dot4(p_a1, yb)))));
    part[1] = fmaf(p_c0.x, ya.x, fmaf(p_c0.y, ya.y, fmaf(p_c0.z, ya.z,
              fmaf(p_c0.w, ya.w, dot4(p_c1, yb)))));

#pragma unroll
    for (int b = 1; b < 4; ++b) {
        const float4 a0 = __ldcs(Wr + (2 * b)     * 64);
        const float4 a1 = __ldcs(Wr + (2 * b)     * 64 + 32);
        const float4 c0 = __ldcs(Wr + (2 * b + 1) * 64);
        const float4 c1 = __ldcs(Wr + (2 * b + 1) * 64 + 32);
        part[2 * b]     = fmaf(a0.x, ya.x, fmaf(a0.y, ya.y, fmaf(a0.z, ya.z,
                          fmaf(a0.w, ya.w, dot4(a1, yb)))));
        part[2 * b + 1] = fmaf(c0.x, ya.x, fmaf(c0.y, ya.y, fmaf(c0.z, ya.z,
                          fmaf(c0.w, ya.w, dot4(c1, yb)))));
    }

    warp_sum8(part);

    __shared__ float sp[4];
    if (lane == 0) {
        const float* b2o = b2 + o * MID_ + row0;
        const float* W3o = W3 + o * MID_ + row0;
        float p = 0.0f;
#pragma unroll
        for (int j = 0; j < 8; ++j)
            p = fmaf(W3o[j], sigmoidf_(part[j] + b2o[j]), p);
        sp[warp] = p;
    }
    __syncthreads();   // convergent barrier
    if (threadIdx.x == 0)
        g_part[chunk * N_OBJ_ + o] = sp[0] + sp[1] + sp[2] + sp[3];
}

// ---- K3: thread-per-object reduction + sigmoid ----
__global__ __launch_bounds__(128)
void k3_final(const float* __restrict__ b3, float* __restrict__ out)
{
    cudaGridDependencySynchronize();

    const int o = blockIdx.x * 128 + threadIdx.x;
    float s = b3[o];
#pragma unroll
    for (int c = 0; c < 8; ++c)
        s += g_part[c * N_OBJ_ + o];
    out[o] = sigmoidf_(s);
}

extern "C" void kernel_launch(void* const* d_in, const int* in_sizes, int n_in,
                              void* d_out, int out_size)
{
    const float* x  = (const float*)d_in[0];
    const float* W1 = (const float*)d_in[1];
    const float* b1 = (const float*)d_in[2];
    const float* W2 = (const float*)d_in[3];
    const float* b2 = (const float*)d_in[4];
    const float* W3 = (const float*)d_in[5];
    const float* b3 = (const float*)d_in[6];
    float* out = (float*)d_out;

    k1_fc1<<<N_OBJ_ * 4, 256>>>(x, W1, b1);

    cudaLaunchAttribute attr[1];
    attr[0].id = cudaLaunchAttributeProgrammaticStreamSerialization;
    attr[0].val.programmaticStreamSerializationAllowed = 1;

    {
        cudaLaunchConfig_t cfg = {};
        cfg.gridDim  = dim3(N_OBJ_ * 8);
        cfg.blockDim = dim3(128);
        cfg.stream   = 0;
        cfg.attrs    = attr;
        cfg.numAttrs = 1;
        cudaLaunchKernelEx(&cfg, k2_fc2, W2, b2, W3);
    }
    {
        cudaLaunchConfig_t cfg = {};
        cfg.gridDim  = dim3(N_OBJ_ / 128);
        cfg.blockDim = dim3(128);
        cfg.stream   = 0;
        cfg.attrs    = attr;
        cfg.numAttrs = 1;
        cudaLaunchKernelEx(&cfg, k3_final, b3, out);
    }
}